// round 2
// baseline (speedup 1.0000x reference)
#include <cuda_runtime.h>
#include <cuda_bf16.h>
#include <cstdint>

#define HQ     32
#define HKV    8
#define DHEAD  128
#define QR     64    // query rows per CTA
#define CK     64    // keys per chunk
#define QSTR   132   // Q/K/P smem row stride (floats): conflict-free frag loads
#define VSTR   136   // V smem row stride
#define NT     256

#define OFF_K (QR*QSTR)              // 8448
#define OFF_V (OFF_K + CK*QSTR)      // 16896
#define OFF_ML (OFF_V + CK*VSTR)     // 25600
#define SMEM_FLOATS (OFF_ML + 256)   // 25856
#define SMEM_BYTES (SMEM_FLOATS * 4) // 103424 B -> 2 CTAs/SM

__device__ __forceinline__ float f2tf32(float x) {
    uint32_t u;
    asm("cvt.rna.tf32.f32 %0, %1;" : "=r"(u) : "f"(x));
    return __uint_as_float(u);
}

__device__ __forceinline__ void mma_tf32(float d[4], const uint32_t a[4], const uint32_t b[2]) {
    asm volatile(
        "mma.sync.aligned.m16n8k8.row.col.f32.tf32.tf32.f32 "
        "{%0,%1,%2,%3}, {%4,%5,%6,%7}, {%8,%9}, {%0,%1,%2,%3};\n"
        : "+f"(d[0]), "+f"(d[1]), "+f"(d[2]), "+f"(d[3])
        : "r"(a[0]), "r"(a[1]), "r"(a[2]), "r"(a[3]),
          "r"(b[0]), "r"(b[1]));
}

// Load a 64x128 fp32 tile gmem->smem with tf32 rounding (and optional scale).
// 256 threads: 8 iterations of float4 per thread.
__device__ __forceinline__ void ldtile(float* __restrict__ dst, int dstride,
                                       const float* __restrict__ src, int sstride,
                                       int tid, float mul) {
    const int r0 = tid >> 5;          // 0..7
    const int c  = (tid & 31) << 2;
#pragma unroll
    for (int it = 0; it < 8; ++it) {
        const int row = (it << 3) + r0;
        const float4 v = *reinterpret_cast<const float4*>(src + (size_t)row * sstride + c);
        float4 w;
        w.x = f2tf32(v.x * mul);
        w.y = f2tf32(v.y * mul);
        w.z = f2tf32(v.z * mul);
        w.w = f2tf32(v.w * mul);
        *reinterpret_cast<float4*>(dst + row * dstride + c) = w;
    }
}

// One 64-key chunk. Warp = (strip s: rows 16s..16s+15) x (key half p: keys 32p..32p+31).
// MODE 0: keys R-128 (valid iff col >  row, local coords)  -> tiles T in [2s, 8)
// MODE 1: keys R-64  (fully valid, no mask)                -> tiles T in [0, 8)
// MODE 2: keys R     (valid iff col <= row)                -> tiles T in [0, 2s+2)
// This warp covers T in [4p, 4p+4) intersected with the above.
template <int MODE>
__device__ __forceinline__ void process_chunk(
    const float* __restrict__ Qs, float* __restrict__ Ks, const float* __restrict__ Vs,
    float (&o)[16][4], float& m0, float& m1, float& l0, float& l1,
    int s, int p, int gq, int tig)
{
    const int glo = (MODE == 0) ? (s << 1) : 0;
    const int ghi = (MODE == 2) ? ((s << 1) + 2) : 8;
    const int r0 = (s << 4) + gq;
    const int r1 = r0 + 8;
    const int arow0 = r0 * QSTR, arow1 = r1 * QSTR;

    float sacc[4][4];
#pragma unroll
    for (int tt = 0; tt < 4; ++tt)
        sacc[tt][0] = sacc[tt][1] = sacc[tt][2] = sacc[tt][3] = 0.f;

    // ---- S = Q @ K^T ----
#pragma unroll 4
    for (int kk = 0; kk < 16; ++kk) {
        const int ac = (kk << 3) + tig;
        uint32_t a[4];
        a[0] = __float_as_uint(Qs[arow0 + ac]);
        a[1] = __float_as_uint(Qs[arow1 + ac]);
        a[2] = __float_as_uint(Qs[arow0 + ac + 4]);
        a[3] = __float_as_uint(Qs[arow1 + ac + 4]);
#pragma unroll
        for (int tt = 0; tt < 4; ++tt) {
            const int T = (p << 2) + tt;
            if (T < glo || T >= ghi) continue;
            const int br = ((T << 3) + gq) * QSTR + ac;
            uint32_t bb[2];
            bb[0] = __float_as_uint(Ks[br]);
            bb[1] = __float_as_uint(Ks[br + 4]);
            mma_tf32(sacc[tt], a, bb);
        }
    }

    // ---- mask + row max ----
    float rmax0 = -1e30f, rmax1 = -1e30f;
#pragma unroll
    for (int tt = 0; tt < 4; ++tt) {
        const int T = (p << 2) + tt;
        if (T < glo || T >= ghi) continue;
        const int cb = (T << 3) + (tig << 1);
#pragma unroll
        for (int e = 0; e < 2; ++e) {
            if (MODE != 1) {
                const int col = cb + e;
                const bool v0 = (MODE == 0) ? (col > r0) : (col <= r0);
                const bool v1 = (MODE == 0) ? (col > r1) : (col <= r1);
                if (!v0) sacc[tt][e]     = -1e30f;
                if (!v1) sacc[tt][2 + e] = -1e30f;
            }
            rmax0 = fmaxf(rmax0, sacc[tt][e]);
            rmax1 = fmaxf(rmax1, sacc[tt][2 + e]);
        }
    }
    rmax0 = fmaxf(rmax0, __shfl_xor_sync(0xffffffffu, rmax0, 1));
    rmax0 = fmaxf(rmax0, __shfl_xor_sync(0xffffffffu, rmax0, 2));
    rmax1 = fmaxf(rmax1, __shfl_xor_sync(0xffffffffu, rmax1, 1));
    rmax1 = fmaxf(rmax1, __shfl_xor_sync(0xffffffffu, rmax1, 2));

    const float mn0 = fmaxf(m0, rmax0);
    const float mn1 = fmaxf(m1, rmax1);
    const float c0 = __expf(m0 - mn0);   // exp(-inf)=0 wipes fully-masked history
    const float c1 = __expf(m1 - mn1);
    m0 = mn0; m1 = mn1;
    l0 *= c0; l1 *= c1;
#pragma unroll
    for (int t = 0; t < 16; ++t) {
        o[t][0] *= c0; o[t][1] *= c0;
        o[t][2] *= c1; o[t][3] *= c1;
    }

    float s0 = 0.f, s1 = 0.f;
#pragma unroll
    for (int tt = 0; tt < 4; ++tt) {
        const int T = (p << 2) + tt;
        if (T < glo || T >= ghi) continue;
        sacc[tt][0] = __expf(sacc[tt][0] - mn0);
        sacc[tt][1] = __expf(sacc[tt][1] - mn0);
        sacc[tt][2] = __expf(sacc[tt][2] - mn1);
        sacc[tt][3] = __expf(sacc[tt][3] - mn1);
        s0 += sacc[tt][0] + sacc[tt][1];
        s1 += sacc[tt][2] + sacc[tt][3];
    }
    l0 += s0; l1 += s1;

    // ---- P -> smem (reuse K buffer). Rows are warp-exclusive; cols too. ----
    __syncthreads();   // all warps done reading K tiles
#pragma unroll
    for (int tt = 0; tt < 4; ++tt) {
        const int T = (p << 2) + tt;
        if (T < glo || T >= ghi) continue;
        const int cb = (T << 3) + (tig << 1);
        *reinterpret_cast<float2*>(&Ks[r0 * QSTR + cb]) =
            make_float2(f2tf32(sacc[tt][0]), f2tf32(sacc[tt][1]));
        *reinterpret_cast<float2*>(&Ks[r1 * QSTR + cb]) =
            make_float2(f2tf32(sacc[tt][2]), f2tf32(sacc[tt][3]));
    }
    __syncwarp();      // P readback is warp-local

    // ---- O += P @ V ----
#pragma unroll
    for (int tt = 0; tt < 4; ++tt) {
        const int T = (p << 2) + tt;
        if (T < glo || T >= ghi) continue;
        const int pc = (T << 3) + tig;
        uint32_t a[4];
        a[0] = __float_as_uint(Ks[arow0 + pc]);
        a[1] = __float_as_uint(Ks[arow1 + pc]);
        a[2] = __float_as_uint(Ks[arow0 + pc + 4]);
        a[3] = __float_as_uint(Ks[arow1 + pc + 4]);
        const int vr = ((T << 3) + tig) * VSTR;
#pragma unroll
        for (int t = 0; t < 16; ++t) {
            const int vb = vr + (t << 3) + gq;
            uint32_t bb[2];
            bb[0] = __float_as_uint(Vs[vb]);
            bb[1] = __float_as_uint(Vs[vb + 4 * VSTR]);
            mma_tf32(o[t], a, bb);
        }
    }
}

__global__ void __launch_bounds__(NT, 2)
fa_swa_kernel(const float* __restrict__ Q, const float* __restrict__ K,
              const float* __restrict__ V, float* __restrict__ Out, int S)
{
    extern __shared__ float sm[];
    float* Qs = sm;
    float* Ks = sm + OFF_K;
    float* Vs = sm + OFF_V;
    float* ML = sm + OFF_ML;   // [m: 2x64][l: 2x64]

    const int n   = blockIdx.x;
    const int hq  = blockIdx.y;
    const int b   = blockIdx.z;
    const int hkv = hq >> 2;
    const int R   = n * QR;

    const int tid  = threadIdx.x;
    const int w    = tid >> 5;
    const int lane = tid & 31;
    const int s    = w >> 1;       // row strip 0..3
    const int p    = w & 1;        // key half 0..1
    const int gq   = lane >> 2;
    const int tig  = lane & 3;
    const int r0   = (s << 4) + gq;
    const int r1   = r0 + 8;

    const float scale = 0.08838834764831845f;  // 1/sqrt(128)

    ldtile(Qs, QSTR, Q + ((size_t)(b * S + R) * HQ + hq) * DHEAD, HQ * DHEAD, tid, scale);

    float o[16][4];
#pragma unroll
    for (int t = 0; t < 16; ++t)
        o[t][0] = o[t][1] = o[t][2] = o[t][3] = 0.f;
    float m0 = -INFINITY, m1 = -INFINITY, l0 = 0.f, l1 = 0.f;

    if (R >= 2 * CK) {
        const int k0 = R - 2 * CK;
        ldtile(Ks, QSTR, K + ((size_t)(b * S + k0) * HKV + hkv) * DHEAD, HKV * DHEAD, tid, 1.f);
        ldtile(Vs, VSTR, V + ((size_t)(b * S + k0) * HKV + hkv) * DHEAD, HKV * DHEAD, tid, 1.f);
        __syncthreads();
        process_chunk<0>(Qs, Ks, Vs, o, m0, m1, l0, l1, s, p, gq, tig);
        __syncthreads();
    }
    if (R >= CK) {
        const int k0 = R - CK;
        ldtile(Ks, QSTR, K + ((size_t)(b * S + k0) * HKV + hkv) * DHEAD, HKV * DHEAD, tid, 1.f);
        ldtile(Vs, VSTR, V + ((size_t)(b * S + k0) * HKV + hkv) * DHEAD, HKV * DHEAD, tid, 1.f);
        __syncthreads();
        process_chunk<1>(Qs, Ks, Vs, o, m0, m1, l0, l1, s, p, gq, tig);
        __syncthreads();
    }
    {
        ldtile(Ks, QSTR, K + ((size_t)(b * S + R) * HKV + hkv) * DHEAD, HKV * DHEAD, tid, 1.f);
        ldtile(Vs, VSTR, V + ((size_t)(b * S + R) * HKV + hkv) * DHEAD, HKV * DHEAD, tid, 1.f);
        __syncthreads();
        process_chunk<2>(Qs, Ks, Vs, o, m0, m1, l0, l1, s, p, gq, tig);
    }

    // ---- split-K merge of the warp pair (p=0: keys lo half, p=1: hi half) ----
    l0 += __shfl_xor_sync(0xffffffffu, l0, 1);
    l0 += __shfl_xor_sync(0xffffffffu, l0, 2);
    l1 += __shfl_xor_sync(0xffffffffu, l1, 1);
    l1 += __shfl_xor_sync(0xffffffffu, l1, 2);

    if (tig == 0) {
        ML[p * 64 + r0] = m0;  ML[p * 64 + r1] = m1;
        ML[128 + p * 64 + r0] = l0;  ML[128 + p * 64 + r1] = l1;
    }
    __syncthreads();   // also: all PV reads of Ks (P) are done -> Ks reusable

    const float mp0 = ML[(1 - p) * 64 + r0];
    const float mp1 = ML[(1 - p) * 64 + r1];
    const float lp0 = ML[128 + (1 - p) * 64 + r0];
    const float lp1 = ML[128 + (1 - p) * 64 + r1];

    const float mn0 = fmaxf(m0, mp0), mn1 = fmaxf(m1, mp1);
    const float a0  = __expf(m0 - mn0),  a1  = __expf(m1 - mn1);
    const float ap0 = __expf(mp0 - mn0), ap1 = __expf(mp1 - mn1);
    const float li0 = 1.f / (l0 * a0 + lp0 * ap0);
    const float li1 = 1.f / (l1 * a1 + lp1 * ap1);

#pragma unroll
    for (int t = 0; t < 16; ++t) {
        o[t][0] *= a0; o[t][1] *= a0;
        o[t][2] *= a1; o[t][3] *= a1;
    }

    // send the half this warp does NOT store: p=0 sends cols 64..127 (tiles 8..15)
    // at buffer col offset 66; p=1 sends cols 0..63 (tiles 0..7) at offset 0.
    const int sendbase = p ? 0 : 8;
    const int sendoff  = p ? 0 : 66;
#pragma unroll
    for (int t = 0; t < 8; ++t) {
        const int tt = sendbase + t;
        const int cb = (t << 3) + (tig << 1) + sendoff;
        *reinterpret_cast<float2*>(&Ks[r0 * QSTR + cb]) = make_float2(o[tt][0], o[tt][1]);
        *reinterpret_cast<float2*>(&Ks[r1 * QSTR + cb]) = make_float2(o[tt][2], o[tt][3]);
    }
    __syncthreads();

    // combine kept half with peer's contribution, normalize, store.
    const int keepbase = p ? 8 : 0;
    const int keepoff  = p ? 66 : 0;
    const int colbase  = p ? 64 : 0;
    float* Op = Out + ((size_t)(b * S + R) * HQ + hq) * DHEAD;
    const size_t rstr = (size_t)HQ * DHEAD;
#pragma unroll
    for (int t = 0; t < 8; ++t) {
        const int cb = (t << 3) + (tig << 1);
        const float2 x0 = *reinterpret_cast<const float2*>(&Ks[r0 * QSTR + cb + keepoff]);
        const float2 x1 = *reinterpret_cast<const float2*>(&Ks[r1 * QSTR + cb + keepoff]);
        const int tt = keepbase + t;
        *reinterpret_cast<float2*>(Op + (size_t)r0 * rstr + colbase + cb) =
            make_float2((o[tt][0] + x0.x) * li0, (o[tt][1] + x0.y) * li0);
        *reinterpret_cast<float2*>(Op + (size_t)r1 * rstr + colbase + cb) =
            make_float2((o[tt][2] + x1.x) * li1, (o[tt][3] + x1.y) * li1);
    }
}

extern "C" void kernel_launch(void* const* d_in, const int* in_sizes, int n_in,
                              void* d_out, int out_size) {
    const float* Q = (const float*)d_in[0];
    const float* K = (const float*)d_in[1];
    const float* V = (const float*)d_in[2];
    float* Out = (float*)d_out;

    const int BS = in_sizes[0] / (HQ * DHEAD);  // B * S
    const int B = 2;
    const int S = BS / B;
    const int nblk = S / QR;

    cudaFuncSetAttribute(fa_swa_kernel,
                         cudaFuncAttributeMaxDynamicSharedMemorySize, SMEM_BYTES);

    dim3 grid(nblk, HQ, B);
    fa_swa_kernel<<<grid, NT, SMEM_BYTES>>>(Q, K, V, Out, S);
}

// round 4
// speedup vs baseline: 1.7338x; 1.7338x over previous
#include <cuda_runtime.h>
#include <cstdint>

#define HQ     32
#define HKV    8
#define DHEAD  128
#define QR     128   // query rows per CTA
#define SUBK   32    // keys per sub-chunk
#define NSUB   8
#define QSTR   132   // Q/K smem row stride (floats): conflict-free frag loads
#define VSTR   136   // V smem row stride
#define PSTR   36    // per-warp P row stride
#define NT     256
#define STAGES 3

#define OFF_KS (QR*QSTR)                  // 16896
#define KSTAGE (SUBK*QSTR)                // 4224
#define OFF_VS (OFF_KS + STAGES*KSTAGE)   // 29568
#define VSTAGE (SUBK*VSTR)                // 4352
#define OFF_P  (OFF_VS + STAGES*VSTAGE)   // 42624
#define PWARP  (16*PSTR)                  // 576
#define SMEM_FLOATS (OFF_P + 8*PWARP)     // 47232
#define SMEM_BYTES (SMEM_FLOATS * 4)      // 188928 B

__device__ __forceinline__ float f2tf32(float x) {
    uint32_t u;
    asm("cvt.rna.tf32.f32 %0, %1;" : "=r"(u) : "f"(x));
    return __uint_as_float(u);
}

__device__ __forceinline__ uint32_t ld_tf32(const float* p) {
    uint32_t u;
    asm("cvt.rna.tf32.f32 %0, %1;" : "=r"(u) : "f"(*p));
    return u;
}

__device__ __forceinline__ void mma_tf32(float d[4], const uint32_t a[4], const uint32_t b[2]) {
    asm volatile(
        "mma.sync.aligned.m16n8k8.row.col.f32.tf32.tf32.f32 "
        "{%0,%1,%2,%3}, {%4,%5,%6,%7}, {%8,%9}, {%0,%1,%2,%3};\n"
        : "+f"(d[0]), "+f"(d[1]), "+f"(d[2]), "+f"(d[3])
        : "r"(a[0]), "r"(a[1]), "r"(a[2]), "r"(a[3]),
          "r"(b[0]), "r"(b[1]));
}

__device__ __forceinline__ void cp16(float* dst, const float* src) {
    uint32_t d = (uint32_t)__cvta_generic_to_shared(dst);
    asm volatile("cp.async.cg.shared.global [%0], [%1], 16;" :: "r"(d), "l"(src));
}

// Prefetch one 32x128 fp32 K tile and V tile (raw bits; cvt at frag load).
__device__ __forceinline__ void issue_sub(const float* __restrict__ Kg,
                                          const float* __restrict__ Vg,
                                          float* __restrict__ sK, float* __restrict__ sV,
                                          int tid) {
    const int r = tid >> 5;           // 0..7
    const int c = (tid & 31) << 2;    // 0..124
#pragma unroll
    for (int it = 0; it < 4; ++it) {
        const int row = (it << 3) + r;
        cp16(sK + row * QSTR + c, Kg + (size_t)row * (HKV * DHEAD) + c);
        cp16(sV + row * VSTR + c, Vg + (size_t)row * (HKV * DHEAD) + c);
    }
}

__global__ void __launch_bounds__(NT, 1)
fa_swa_kernel(const float* __restrict__ Q, const float* __restrict__ K,
              const float* __restrict__ V, float* __restrict__ Out, int S)
{
    extern __shared__ float sm[];
    float* Qs = sm;

    const int n   = blockIdx.x;
    const int hq  = blockIdx.y;
    const int b   = blockIdx.z;
    const int hkv = hq >> 2;
    const int R   = n * QR;

    const int tid  = threadIdx.x;
    const int w    = tid >> 5;     // warp = row strip (16 rows)
    const int lane = tid & 31;
    const int gq   = lane >> 2;
    const int tig  = lane & 3;
    const int r0   = (w << 4) + gq;
    const int r1   = r0 + 8;
    const int arow0 = r0 * QSTR, arow1 = r1 * QSTR;

    const float scale = 0.08838834764831845f;  // 1/sqrt(128)

    // ---- Q: gmem -> smem with tf32 rounding + scale (LDG; overlaps cp.async below) ----
    {
        const float* Qp = Q + ((size_t)(b * S + R) * HQ + hq) * DHEAD;
        const int rr = tid >> 5;
        const int c  = (lane) << 2;
#pragma unroll
        for (int it = 0; it < 16; ++it) {
            const int row = (it << 3) + rr;
            const float4 v = *reinterpret_cast<const float4*>(Qp + (size_t)row * (HQ * DHEAD) + c);
            float4 t;
            t.x = f2tf32(v.x * scale);
            t.y = f2tf32(v.y * scale);
            t.z = f2tf32(v.z * scale);
            t.w = f2tf32(v.w * scale);
            *reinterpret_cast<float4*>(Qs + row * QSTR + c) = t;
        }
    }

    const int jstart = (R == 0) ? 4 : 0;   // sub-chunk j covers keys R-128+32j .. +31
    const float* KB = K + ((size_t)b * S * HKV + hkv) * DHEAD;
    const float* VB = V + ((size_t)b * S * HKV + hkv) * DHEAD;

    // ---- pipeline prologue: 3 stages in flight ----
#pragma unroll
    for (int i = 0; i < STAGES; ++i) {
        const int j = jstart + i;
        const int key0 = R - 128 + 32 * j;
        issue_sub(KB + (size_t)key0 * HKV * DHEAD, VB + (size_t)key0 * HKV * DHEAD,
                  sm + OFF_KS + (j % STAGES) * KSTAGE,
                  sm + OFF_VS + (j % STAGES) * VSTAGE, tid);
        asm volatile("cp.async.commit_group;");
    }

    float o[16][4];
#pragma unroll
    for (int t = 0; t < 16; ++t)
        o[t][0] = o[t][1] = o[t][2] = o[t][3] = 0.f;
    float m0 = -INFINITY, m1 = -INFINITY, l0 = 0.f, l1 = 0.f;

    float* Pw = sm + OFF_P + w * PWARP;

    for (int j = jstart; j < NSUB; ++j) {
        asm volatile("cp.async.wait_group %0;" :: "n"(STAGES - 1));
        __syncthreads();

        const float* Ks = sm + OFF_KS + (j % STAGES) * KSTAGE;
        const float* Vs = sm + OFF_VS + (j % STAGES) * VSTAGE;
        const int d0 = 32 * j - 128;   // key offset of col 0 relative to R

        // strip active iff band overlaps: rows [16w,16w+15], keys d in [d0, d0+31]
        const bool any = (32 * j <= 16 * w + 143) && (32 * j >= 16 * w - 30);

        if (any) {
            float sacc[4][4];
#pragma unroll
            for (int t = 0; t < 4; ++t)
                sacc[t][0] = sacc[t][1] = sacc[t][2] = sacc[t][3] = 0.f;

            // ---- S = Q @ K^T (dense 16 rows x 32 keys) ----
#pragma unroll 4
            for (int kk = 0; kk < 16; ++kk) {
                const int ac = (kk << 3) + tig;
                uint32_t a[4];
                a[0] = __float_as_uint(Qs[arow0 + ac]);
                a[1] = __float_as_uint(Qs[arow1 + ac]);
                a[2] = __float_as_uint(Qs[arow0 + ac + 4]);
                a[3] = __float_as_uint(Qs[arow1 + ac + 4]);
#pragma unroll
                for (int t = 0; t < 4; ++t) {
                    const int br = ((t << 3) + gq) * QSTR + ac;
                    uint32_t bb[2] = { ld_tf32(&Ks[br]), ld_tf32(&Ks[br + 4]) };
                    mma_tf32(sacc[t], a, bb);
                }
            }

            // ---- elementwise band mask + row max ----
            float rmax0 = -1e30f, rmax1 = -1e30f;
#pragma unroll
            for (int t = 0; t < 4; ++t) {
                const int cb = d0 + (t << 3) + (tig << 1);
#pragma unroll
                for (int e = 0; e < 2; ++e) {
                    const int d = cb + e;
                    if (!(d <= r0 && d >= r0 - 127)) sacc[t][e]     = -1e30f;
                    if (!(d <= r1 && d >= r1 - 127)) sacc[t][2 + e] = -1e30f;
                    rmax0 = fmaxf(rmax0, sacc[t][e]);
                    rmax1 = fmaxf(rmax1, sacc[t][2 + e]);
                }
            }
            rmax0 = fmaxf(rmax0, __shfl_xor_sync(0xffffffffu, rmax0, 1));
            rmax0 = fmaxf(rmax0, __shfl_xor_sync(0xffffffffu, rmax0, 2));
            rmax1 = fmaxf(rmax1, __shfl_xor_sync(0xffffffffu, rmax1, 1));
            rmax1 = fmaxf(rmax1, __shfl_xor_sync(0xffffffffu, rmax1, 2));

            const float mn0 = fmaxf(m0, rmax0);
            const float mn1 = fmaxf(m1, rmax1);
            const float c0 = __expf(m0 - mn0);   // exp(-inf)=0 wipes empty history
            const float c1 = __expf(m1 - mn1);
            m0 = mn0; m1 = mn1;

            float s0 = 0.f, s1 = 0.f;
#pragma unroll
            for (int t = 0; t < 4; ++t) {
                sacc[t][0] = __expf(sacc[t][0] - mn0);
                sacc[t][1] = __expf(sacc[t][1] - mn0);
                sacc[t][2] = __expf(sacc[t][2] - mn1);
                sacc[t][3] = __expf(sacc[t][3] - mn1);
                s0 += sacc[t][0] + sacc[t][1];
                s1 += sacc[t][2] + sacc[t][3];
            }
            l0 = l0 * c0 + s0;    // per-thread partial; quad-reduced once at end
            l1 = l1 * c1 + s1;
#pragma unroll
            for (int t = 0; t < 16; ++t) {
                o[t][0] *= c0; o[t][1] *= c0;
                o[t][2] *= c1; o[t][3] *= c1;
            }

            // ---- P -> warp-local smem (accumulator layout -> A-frag layout) ----
#pragma unroll
            for (int t = 0; t < 4; ++t) {
                const int cb = (t << 3) + (tig << 1);
                *reinterpret_cast<float2*>(&Pw[gq * PSTR + cb]) =
                    make_float2(f2tf32(sacc[t][0]), f2tf32(sacc[t][1]));
                *reinterpret_cast<float2*>(&Pw[(gq + 8) * PSTR + cb]) =
                    make_float2(f2tf32(sacc[t][2]), f2tf32(sacc[t][3]));
            }
            __syncwarp();

            // ---- O += P @ V (dense) ----
#pragma unroll
            for (int kp = 0; kp < 4; ++kp) {
                const int pc = (kp << 3) + tig;
                uint32_t a[4];
                a[0] = __float_as_uint(Pw[gq * PSTR + pc]);
                a[1] = __float_as_uint(Pw[(gq + 8) * PSTR + pc]);
                a[2] = __float_as_uint(Pw[gq * PSTR + pc + 4]);
                a[3] = __float_as_uint(Pw[(gq + 8) * PSTR + pc + 4]);
                const int vr = ((kp << 3) + tig) * VSTR;
#pragma unroll
                for (int t = 0; t < 16; ++t) {
                    const int vb = vr + (t << 3) + gq;
                    uint32_t bb[2] = { ld_tf32(&Vs[vb]), ld_tf32(&Vs[vb + 4 * VSTR]) };
                    mma_tf32(o[t], a, bb);
                }
            }
        }

        __syncthreads();   // all warps done with stage j before its buffer is refilled
        {
            const int jn = j + STAGES;
            if (jn < NSUB) {
                const int key0 = R - 128 + 32 * jn;
                issue_sub(KB + (size_t)key0 * HKV * DHEAD, VB + (size_t)key0 * HKV * DHEAD,
                          sm + OFF_KS + (jn % STAGES) * KSTAGE,
                          sm + OFF_VS + (jn % STAGES) * VSTAGE, tid);
            }
            asm volatile("cp.async.commit_group;");  // empty group keeps wait_group counting
        }
    }

    // ---- finalize: quad-reduce l, normalize, store ----
    l0 += __shfl_xor_sync(0xffffffffu, l0, 1);
    l0 += __shfl_xor_sync(0xffffffffu, l0, 2);
    l1 += __shfl_xor_sync(0xffffffffu, l1, 1);
    l1 += __shfl_xor_sync(0xffffffffu, l1, 2);
    const float inv0 = 1.f / l0;
    const float inv1 = 1.f / l1;

    float* Op = Out + ((size_t)(b * S + R) * HQ + hq) * DHEAD;
    const size_t rstr = (size_t)HQ * DHEAD;
#pragma unroll
    for (int t = 0; t < 16; ++t) {
        const int cb = (t << 3) + (tig << 1);
        *reinterpret_cast<float2*>(Op + (size_t)r0 * rstr + cb) =
            make_float2(o[t][0] * inv0, o[t][1] * inv0);
        *reinterpret_cast<float2*>(Op + (size_t)r1 * rstr + cb) =
            make_float2(o[t][2] * inv1, o[t][3] * inv1);
    }
}

extern "C" void kernel_launch(void* const* d_in, const int* in_sizes, int n_in,
                              void* d_out, int out_size) {
    const float* Q = (const float*)d_in[0];
    const float* K = (const float*)d_in[1];
    const float* V = (const float*)d_in[2];
    float* Out = (float*)d_out;

    const int BS = in_sizes[0] / (HQ * DHEAD);  // B * S
    const int B = 2;
    const int S = BS / B;
    const int nblk = S / QR;

    cudaFuncSetAttribute(fa_swa_kernel,
                         cudaFuncAttributeMaxDynamicSharedMemorySize, SMEM_BYTES);

    dim3 grid(nblk, HQ, B);
    fa_swa_kernel<<<grid, NT, SMEM_BYTES>>>(Q, K, V, Out, S);
}

// round 5
// speedup vs baseline: 1.7451x; 1.0065x over previous
#include <cuda_runtime.h>
#include <cstdint>

#define HQ     32
#define HKV    8
#define DHEAD  128
#define QR     128   // query rows per CTA
#define SUBK   32    // keys per sub-chunk
#define NSUB   8
#define QSTR   132   // Q/K smem row stride (floats)
#define VSTR   136   // V smem row stride
#define PSTR   36    // per-strip P row stride
#define NT     512
#define STAGES 3

#define OFF_KS (QR*QSTR)                  // 16896
#define KSTAGE (SUBK*QSTR)                // 4224
#define OFF_VS (OFF_KS + STAGES*KSTAGE)   // 29568
#define VSTAGE (SUBK*VSTR)                // 4352
#define OFF_P  (OFF_VS + STAGES*VSTAGE)   // 42624
#define PSTRIP (16*PSTR)                  // 576
#define OFF_ML (OFF_P + 8*PSTRIP)         // 47232
#define SMEM_FLOATS (OFF_ML + 256)        // 47488
#define SMEM_BYTES (SMEM_FLOATS * 4)      // 189952 B

__device__ __forceinline__ float f2tf32(float x) {
    uint32_t u;
    asm("cvt.rna.tf32.f32 %0, %1;" : "=r"(u) : "f"(x));
    return __uint_as_float(u);
}

__device__ __forceinline__ uint32_t ld_tf32(const float* p) {
    uint32_t u;
    asm("cvt.rna.tf32.f32 %0, %1;" : "=r"(u) : "f"(*p));
    return u;
}

__device__ __forceinline__ void mma_tf32(float d[4], const uint32_t a[4], const uint32_t b[2]) {
    asm volatile(
        "mma.sync.aligned.m16n8k8.row.col.f32.tf32.tf32.f32 "
        "{%0,%1,%2,%3}, {%4,%5,%6,%7}, {%8,%9}, {%0,%1,%2,%3};\n"
        : "+f"(d[0]), "+f"(d[1]), "+f"(d[2]), "+f"(d[3])
        : "r"(a[0]), "r"(a[1]), "r"(a[2]), "r"(a[3]),
          "r"(b[0]), "r"(b[1]));
}

__device__ __forceinline__ void cp16(float* dst, const float* src) {
    uint32_t d = (uint32_t)__cvta_generic_to_shared(dst);
    asm volatile("cp.async.cg.shared.global [%0], [%1], 16;" :: "r"(d), "l"(src));
}

// Prefetch one 32x128 fp32 K tile and V tile. 512 threads: 2 cp16 each per tensor.
__device__ __forceinline__ void issue_sub(const float* __restrict__ Kg,
                                          const float* __restrict__ Vg,
                                          float* __restrict__ sK, float* __restrict__ sV,
                                          int tid) {
    const int r = tid >> 5;           // 0..15
    const int c = (tid & 31) << 2;    // 0..124
#pragma unroll
    for (int it = 0; it < 2; ++it) {
        const int row = (it << 4) + r;
        cp16(sK + row * QSTR + c, Kg + (size_t)row * (HKV * DHEAD) + c);
        cp16(sV + row * VSTR + c, Vg + (size_t)row * (HKV * DHEAD) + c);
    }
}

__global__ void __launch_bounds__(NT, 1)
fa_swa_kernel(const float* __restrict__ Q, const float* __restrict__ K,
              const float* __restrict__ V, float* __restrict__ Out, int S)
{
    extern __shared__ float sm[];
    float* Qs = sm;
    float* ML = sm + OFF_ML;

    const int n   = blockIdx.x;
    const int hq  = blockIdx.y;
    const int b   = blockIdx.z;
    const int hkv = hq >> 2;
    const int R   = n * QR;

    const int tid  = threadIdx.x;
    const int w    = tid >> 5;
    const int s    = w >> 1;       // row strip 0..7 (16 rows)
    const int h    = w & 1;        // key half (QK) / D half (PV)
    const int lane = tid & 31;
    const int gq   = lane >> 2;
    const int tig  = lane & 3;
    const int r0   = (s << 4) + gq;
    const int r1   = r0 + 8;
    const int arow0 = r0 * QSTR, arow1 = r1 * QSTR;
    const int mlidx = (((s << 1) | h) << 3) | gq;          // own slot
    const int mlpeer = (((s << 1) | (1 - h)) << 3) | gq;   // peer slot

    const float scale = 0.08838834764831845f;  // 1/sqrt(128)

    // ---- Q: gmem -> smem with tf32 rounding + scale ----
    {
        const float* Qp = Q + ((size_t)(b * S + R) * HQ + hq) * DHEAD;
        const int rr = tid >> 5;           // 0..15
        const int c  = lane << 2;
#pragma unroll
        for (int it = 0; it < 8; ++it) {
            const int row = (it << 4) + rr;
            const float4 v = *reinterpret_cast<const float4*>(Qp + (size_t)row * (HQ * DHEAD) + c);
            float4 t;
            t.x = f2tf32(v.x * scale);
            t.y = f2tf32(v.y * scale);
            t.z = f2tf32(v.z * scale);
            t.w = f2tf32(v.w * scale);
            *reinterpret_cast<float4*>(Qs + row * QSTR + c) = t;
        }
    }

    const int jstart = (R == 0) ? 4 : 0;   // sub-chunk j covers keys R-128+32j .. +31
    const float* KB = K + ((size_t)b * S * HKV + hkv) * DHEAD;
    const float* VB = V + ((size_t)b * S * HKV + hkv) * DHEAD;

#pragma unroll
    for (int i = 0; i < STAGES; ++i) {
        const int j = jstart + i;
        const int key0 = R - 128 + 32 * j;
        issue_sub(KB + (size_t)key0 * HKV * DHEAD, VB + (size_t)key0 * HKV * DHEAD,
                  sm + OFF_KS + (j % STAGES) * KSTAGE,
                  sm + OFF_VS + (j % STAGES) * VSTAGE, tid);
        asm volatile("cp.async.commit_group;");
    }

    float o[8][4];                  // 16 rows x 64 D-cols (own half)
#pragma unroll
    for (int t = 0; t < 8; ++t)
        o[t][0] = o[t][1] = o[t][2] = o[t][3] = 0.f;
    float m0 = -INFINITY, m1 = -INFINITY, l0 = 0.f, l1 = 0.f;

    float* Ps = sm + OFF_P + s * PSTRIP;   // strip-shared P (32 keys)

    for (int j = jstart; j < NSUB; ++j) {
        asm volatile("cp.async.wait_group %0;" :: "n"(STAGES - 1));
        __syncthreads();   // A: stage j visible

        const float* Ks = sm + OFF_KS + (j % STAGES) * KSTAGE;
        const float* Vs = sm + OFF_VS + (j % STAGES) * VSTAGE;
        const int d0 = 32 * j - 128;

        const bool any = (32 * j <= 16 * s + 143) && (32 * j >= 16 * s - 30);

        float sacc[2][4];
        float rmax0 = -1e30f, rmax1 = -1e30f;

        if (any) {
            sacc[0][0] = sacc[0][1] = sacc[0][2] = sacc[0][3] = 0.f;
            sacc[1][0] = sacc[1][1] = sacc[1][2] = sacc[1][3] = 0.f;

            // ---- S(own 16-key half) = Q @ K^T : tiles T = 2h, 2h+1 ----
#pragma unroll 4
            for (int kk = 0; kk < 16; ++kk) {
                const int ac = (kk << 3) + tig;
                uint32_t a[4];
                a[0] = __float_as_uint(Qs[arow0 + ac]);
                a[1] = __float_as_uint(Qs[arow1 + ac]);
                a[2] = __float_as_uint(Qs[arow0 + ac + 4]);
                a[3] = __float_as_uint(Qs[arow1 + ac + 4]);
#pragma unroll
                for (int t = 0; t < 2; ++t) {
                    const int br = ((((h << 1) + t) << 3) + gq) * QSTR + ac;
                    uint32_t bb[2] = { ld_tf32(&Ks[br]), ld_tf32(&Ks[br + 4]) };
                    mma_tf32(sacc[t], a, bb);
                }
            }

            // ---- band mask + row max over own half ----
#pragma unroll
            for (int t = 0; t < 2; ++t) {
                const int cb = d0 + (((h << 1) + t) << 3) + (tig << 1);
#pragma unroll
                for (int e = 0; e < 2; ++e) {
                    const int d = cb + e;
                    if (!(d <= r0 && d >= r0 - 127)) sacc[t][e]     = -1e30f;
                    if (!(d <= r1 && d >= r1 - 127)) sacc[t][2 + e] = -1e30f;
                    rmax0 = fmaxf(rmax0, sacc[t][e]);
                    rmax1 = fmaxf(rmax1, sacc[t][2 + e]);
                }
            }
            rmax0 = fmaxf(rmax0, __shfl_xor_sync(0xffffffffu, rmax0, 1));
            rmax0 = fmaxf(rmax0, __shfl_xor_sync(0xffffffffu, rmax0, 2));
            rmax1 = fmaxf(rmax1, __shfl_xor_sync(0xffffffffu, rmax1, 1));
            rmax1 = fmaxf(rmax1, __shfl_xor_sync(0xffffffffu, rmax1, 2));

            if (tig == 0)
                *reinterpret_cast<float2*>(&ML[mlidx * 2]) = make_float2(rmax0, rmax1);
        }
        __syncthreads();   // B: rmax exchange

        if (any) {
            const float2 pr = *reinterpret_cast<const float2*>(&ML[mlpeer * 2]);
            const float mn0 = fmaxf(m0, fmaxf(rmax0, pr.x));
            const float mn1 = fmaxf(m1, fmaxf(rmax1, pr.y));
            const float c0 = __expf(m0 - mn0);
            const float c1 = __expf(m1 - mn1);
            m0 = mn0; m1 = mn1;

            float s0 = 0.f, s1 = 0.f;
#pragma unroll
            for (int t = 0; t < 2; ++t) {
                sacc[t][0] = __expf(sacc[t][0] - mn0);
                sacc[t][1] = __expf(sacc[t][1] - mn0);
                sacc[t][2] = __expf(sacc[t][2] - mn1);
                sacc[t][3] = __expf(sacc[t][3] - mn1);
                s0 += sacc[t][0] + sacc[t][1];
                s1 += sacc[t][2] + sacc[t][3];
            }
            l0 = l0 * c0 + s0;   // own-half partial; merged with peer at the end
            l1 = l1 * c1 + s1;
#pragma unroll
            for (int t = 0; t < 8; ++t) {
                o[t][0] *= c0; o[t][1] *= c0;
                o[t][2] *= c1; o[t][3] *= c1;
            }

            // P(own half) -> strip-shared smem, cols [16h, 16h+16)
#pragma unroll
            for (int t = 0; t < 2; ++t) {
                const int cb = (((h << 1) + t) << 3) + (tig << 1);
                *reinterpret_cast<float2*>(&Ps[gq * PSTR + cb]) =
                    make_float2(f2tf32(sacc[t][0]), f2tf32(sacc[t][1]));
                *reinterpret_cast<float2*>(&Ps[(gq + 8) * PSTR + cb]) =
                    make_float2(f2tf32(sacc[t][2]), f2tf32(sacc[t][3]));
            }
        }
        __syncthreads();   // C: full P ready

        if (any) {
            // ---- O(own 64 D-cols) += P(32 keys) @ V ----
#pragma unroll
            for (int kp = 0; kp < 4; ++kp) {
                const int pc = (kp << 3) + tig;
                uint32_t a[4];
                a[0] = __float_as_uint(Ps[gq * PSTR + pc]);
                a[1] = __float_as_uint(Ps[(gq + 8) * PSTR + pc]);
                a[2] = __float_as_uint(Ps[gq * PSTR + pc + 4]);
                a[3] = __float_as_uint(Ps[(gq + 8) * PSTR + pc + 4]);
                const int vr = ((kp << 3) + tig) * VSTR;
#pragma unroll
                for (int t = 0; t < 8; ++t) {
                    const int vb = vr + (h << 6) + (t << 3) + gq;
                    uint32_t bb[2] = { ld_tf32(&Vs[vb]), ld_tf32(&Vs[vb + 4 * VSTR]) };
                    mma_tf32(o[t], a, bb);
                }
            }
        }

        __syncthreads();   // D: stage j fully consumed before refill
        {
            const int jn = j + STAGES;
            if (jn < NSUB) {
                const int key0 = R - 128 + 32 * jn;
                issue_sub(KB + (size_t)key0 * HKV * DHEAD, VB + (size_t)key0 * HKV * DHEAD,
                          sm + OFF_KS + (jn % STAGES) * KSTAGE,
                          sm + OFF_VS + (jn % STAGES) * VSTAGE, tid);
            }
            asm volatile("cp.async.commit_group;");
        }
    }

    // ---- finalize: quad-reduce own l, merge with peer half, normalize, store ----
    l0 += __shfl_xor_sync(0xffffffffu, l0, 1);
    l0 += __shfl_xor_sync(0xffffffffu, l0, 2);
    l1 += __shfl_xor_sync(0xffffffffu, l1, 1);
    l1 += __shfl_xor_sync(0xffffffffu, l1, 2);

    if (tig == 0)
        *reinterpret_cast<float2*>(&ML[mlidx * 2]) = make_float2(l0, l1);
    __syncthreads();
    const float2 lp = *reinterpret_cast<const float2*>(&ML[mlpeer * 2]);
    const float inv0 = 1.f / (l0 + lp.x);
    const float inv1 = 1.f / (l1 + lp.y);

    float* Op = Out + ((size_t)(b * S + R) * HQ + hq) * DHEAD;
    const size_t rstr = (size_t)HQ * DHEAD;
#pragma unroll
    for (int t = 0; t < 8; ++t) {
        const int cb = (h << 6) + (t << 3) + (tig << 1);
        *reinterpret_cast<float2*>(Op + (size_t)r0 * rstr + cb) =
            make_float2(o[t][0] * inv0, o[t][1] * inv0);
        *reinterpret_cast<float2*>(Op + (size_t)r1 * rstr + cb) =
            make_float2(o[t][2] * inv1, o[t][3] * inv1);
    }
}

extern "C" void kernel_launch(void* const* d_in, const int* in_sizes, int n_in,
                              void* d_out, int out_size) {
    const float* Q = (const float*)d_in[0];
    const float* K = (const float*)d_in[1];
    const float* V = (const float*)d_in[2];
    float* Out = (float*)d_out;

    const int BS = in_sizes[0] / (HQ * DHEAD);  // B * S
    const int B = 2;
    const int S = BS / B;
    const int nblk = S / QR;

    cudaFuncSetAttribute(fa_swa_kernel,
                         cudaFuncAttributeMaxDynamicSharedMemorySize, SMEM_BYTES);

    dim3 grid(nblk, HQ, B);
    fa_swa_kernel<<<grid, NT, SMEM_BYTES>>>(Q, K, V, Out, S);
}